// round 5
// baseline (speedup 1.0000x reference)
#include <cuda_runtime.h>

// RvNN fused kernel v4: k-pair packed f32x2 FMA (acc halves = k-even/k-odd
// partials). Prepacked weights (global scratch) -> LDS.64 weight loads, zero
// duplication MOVs, no swizzle, cp.async double-buffered tiles.

#define DEVINL __device__ __forceinline__
typedef unsigned long long u64;

constexpr int NTH = 512;
constexpr int BB  = 16;

// packed weight segments (float2 units) in g_packed
constexpr int OP_WC2 = 0;       // 64 kp x 256
constexpr int OP_WP2 = 16384;   // 64 kp x 256
constexpr int OP_WL1 = 32768;   // 256 kp x 128
constexpr int NPACK  = 65536;   // 512 KB

__device__ __align__(16) float2 g_packed[NPACK];

// ---- shared memory layout (float offsets) ----
constexpr int SM_U    = 0;        // U / V / H (row-major [64][128]): 8192
constexpr int SM_CHPA = 8192;     // [64][512] row-major: 32768 (X staging aliases)
constexpr int SM_WT   = 40960;    // 8192 floats = 2 bufs x 2048 u64 (32KB)
constexpr int SM_Y    = 49152;    // 768
constexpr int SM_S12  = 49920;    // 768
constexpr int SM_TOT  = 50688;    // 202752 bytes

DEVINL float sanf(float x) {
    if (isnan(x)) return 0.0f;
    if (isinf(x)) return 9999.0f;
    return x;
}

DEVINL float fast_tanh(float x) {
    float ax = fabsf(x) * 2.8853900817779268f;  // 2*log2(e)
    float e; asm("ex2.approx.f32 %0, %1;" : "=f"(e) : "f"(ax));
    float r; asm("rcp.approx.f32 %0, %1;" : "=f"(r) : "f"(e + 1.0f));
    float t = fmaf(-2.0f, r, 1.0f);
    return copysignf(t, x);
}

DEVINL void fma2(u64& acc, u64 a, u64 b) {
    asm("fma.rn.f32x2 %0, %1, %2, %0;" : "+l"(acc) : "l"(a), "l"(b));
}
DEVINL float2 unpk(u64 v) {
    float2 r; asm("mov.b64 {%0, %1}, %2;" : "=f"(r.x), "=f"(r.y) : "l"(v)); return r;
}

DEVINL void cpa16(void* dst, const void* src) {
    unsigned sa = (unsigned)__cvta_generic_to_shared(dst);
    asm volatile("cp.async.cg.shared.global [%0], [%1], 16;" :: "r"(sa), "l"(src));
}
DEVINL void cpa_commit() { asm volatile("cp.async.commit_group;"); }
DEVINL void cpa_wait0()  { asm volatile("cp.async.wait_group 0;"); }

// ---------- prepack: W[K][N] -> g_packed[kp][c] = (W[2kp][c], W[2kp+1][c]) ----------
__global__ void prepack_kernel(const float* __restrict__ Wc2,
                               const float* __restrict__ Wp2,
                               const float* __restrict__ Wl1)
{
    int idx = blockIdx.x * blockDim.x + threadIdx.x;
    if (idx >= NPACK) return;
    const float* W; int loc, N;
    if (idx < OP_WP2)      { W = Wc2; loc = idx;           N = 256; }
    else if (idx < OP_WL1) { W = Wp2; loc = idx - OP_WP2;  N = 256; }
    else                   { W = Wl1; loc = idx - OP_WL1;  N = 128; }
    int kp = (N == 256) ? (loc >> 8) : (loc >> 7);
    int c  = loc & (N - 1);
    g_packed[idx] = make_float2(W[(2 * kp) * N + c], W[(2 * kp + 1) * N + c]);
}

// ---------- layer1: A[M][KA] @ W[KA][128] + b -> prelu -> U row-major ----------
template<int M, int KA>
DEVINL void layer1(const float* __restrict__ A, const float* __restrict__ WT,
                   const float* __restrict__ bg, float alpha,
                   float* __restrict__ U, int tx, int ty)
{
    constexpr int RPT = M / 16;
    float acc[RPT][4];
#pragma unroll
    for (int r = 0; r < RPT; r++)
#pragma unroll
        for (int j = 0; j < 4; j++) acc[r][j] = 0.0f;

#pragma unroll
    for (int k = 0; k < KA; k += 4) {
        float a[RPT][4];
#pragma unroll
        for (int r = 0; r < RPT; r++) {
            float4 v = *(const float4*)&A[(ty * RPT + r) * KA + k];
            a[r][0] = v.x; a[r][1] = v.y; a[r][2] = v.z; a[r][3] = v.w;
        }
#pragma unroll
        for (int j4 = 0; j4 < 4; j4++) {
            float w[4];
#pragma unroll
            for (int j = 0; j < 4; j++) w[j] = WT[(k + j4) * 128 + tx + 32 * j];
#pragma unroll
            for (int r = 0; r < RPT; r++)
#pragma unroll
                for (int j = 0; j < 4; j++)
                    acc[r][j] = fmaf(a[r][j4], w[j], acc[r][j]);
        }
    }
#pragma unroll
    for (int r = 0; r < RPT; r++)
#pragma unroll
        for (int j = 0; j < 4; j++) {
            int c = tx + 32 * j;
            float v = acc[r][j] + bg[c];
            v = (v >= 0.0f) ? v : alpha * v;
            U[(ty * RPT + r) * 128 + c] = v;
        }
}

// ---------- layer2: U[M][128] @ W[128][256] + b -> tanh -> CHPA[:, colOff..+256) ----------
// k-pair packed: acc halves = k-even/odd partials. cols c = cidx, cidx+128.
template<int M>
DEVINL void layer2(const float* __restrict__ U, const float2* __restrict__ Pg,
                   const float* __restrict__ bg, float* __restrict__ CH, int colOff,
                   u64* __restrict__ WT, int tid)
{
    constexpr int RPT = M / 4;
    const int cidx = tid & 127;
    const int r0 = (tid >> 7) * RPT;
    const float bias0 = bg[cidx], bias1 = bg[cidx + 128];

    u64 acc[RPT][2];
#pragma unroll
    for (int r = 0; r < RPT; r++) { acc[r][0] = 0ull; acc[r][1] = 0ull; }

    // preload tile 0 (8 kp x 256 = 2048 u64 = 16KB -> 1024 x 16B)
    for (int s = tid; s < 1024; s += NTH)
        cpa16(WT + s * 2, Pg + s * 2);
    cpa_commit(); cpa_wait0();
    __syncthreads();

    for (int t = 0; t < 8; t++) {
        const u64* wt = WT + (t & 1) * 2048;
        if (t + 1 < 8) {
            u64* nb = WT + ((t + 1) & 1) * 2048;
            const float2* ns = Pg + (t + 1) * 2048;
            for (int s = tid; s < 1024; s += NTH)
                cpa16(nb + s * 2, ns + s * 2);
            cpa_commit();
        }
#pragma unroll
        for (int kpp = 0; kpp < 8; kpp += 2) {
            u64 w00 = wt[kpp * 256 + cidx];
            u64 w01 = wt[kpp * 256 + cidx + 128];
            u64 w10 = wt[(kpp + 1) * 256 + cidx];
            u64 w11 = wt[(kpp + 1) * 256 + cidx + 128];
            const int kf = 2 * (t * 8 + kpp);  // float offset (16B aligned)
#pragma unroll
            for (int r = 0; r < RPT; r++) {
                ulonglong2 a = *(const ulonglong2*)&U[(r0 + r) * 128 + kf];
                fma2(acc[r][0], a.x, w00);
                fma2(acc[r][1], a.x, w01);
                fma2(acc[r][0], a.y, w10);
                fma2(acc[r][1], a.y, w11);
            }
        }
        cpa_wait0();
        __syncthreads();
    }
#pragma unroll
    for (int r = 0; r < RPT; r++) {
        float2 v0 = unpk(acc[r][0]);
        float2 v1 = unpk(acc[r][1]);
        CH[(r0 + r) * 512 + colOff + cidx]       = fast_tanh(v0.x + v0.y + bias0);
        CH[(r0 + r) * 512 + colOff + cidx + 128] = fast_tanh(v1.x + v1.y + bias1);
    }
}

// ---------- layer3: CHPA[M][512] @ Wl1[512][128] + b -> tanh -> H[M][128] ----------
template<int M>
DEVINL void layer3(const float* __restrict__ CP, const float2* __restrict__ Pg,
                   const float* __restrict__ bl1, float* __restrict__ H,
                   u64* __restrict__ WT, int tid)
{
    constexpr int RPT = M / 8;
    const int cidx = tid & 63;
    const int r0 = (tid >> 6) * RPT;
    const float bias0 = bl1[cidx], bias1 = bl1[cidx + 64];

    u64 acc[RPT][2];
#pragma unroll
    for (int r = 0; r < RPT; r++) { acc[r][0] = 0ull; acc[r][1] = 0ull; }

    // tiles: 16 kp x 128 = 2048 u64 = 16KB, 16 tiles
    for (int s = tid; s < 1024; s += NTH)
        cpa16(WT + s * 2, Pg + s * 2);
    cpa_commit(); cpa_wait0();
    __syncthreads();

    for (int t = 0; t < 16; t++) {
        const u64* wt = WT + (t & 1) * 2048;
        if (t + 1 < 16) {
            u64* nb = WT + ((t + 1) & 1) * 2048;
            const float2* ns = Pg + (t + 1) * 2048;
            for (int s = tid; s < 1024; s += NTH)
                cpa16(nb + s * 2, ns + s * 2);
            cpa_commit();
        }
#pragma unroll
        for (int kpp = 0; kpp < 16; kpp += 2) {
            u64 w00 = wt[kpp * 128 + cidx];
            u64 w01 = wt[kpp * 128 + cidx + 64];
            u64 w10 = wt[(kpp + 1) * 128 + cidx];
            u64 w11 = wt[(kpp + 1) * 128 + cidx + 64];
            const int kf = 2 * (t * 16 + kpp);
#pragma unroll
            for (int r = 0; r < RPT; r++) {
                ulonglong2 a = *(const ulonglong2*)&CP[(r0 + r) * 512 + kf];
                fma2(acc[r][0], a.x, w00);
                fma2(acc[r][1], a.x, w01);
                fma2(acc[r][0], a.y, w10);
                fma2(acc[r][1], a.y, w11);
            }
        }
        cpa_wait0();
        __syncthreads();
    }
#pragma unroll
    for (int r = 0; r < RPT; r++) {
        float2 v0 = unpk(acc[r][0]);
        float2 v1 = unpk(acc[r][1]);
        H[(r0 + r) * 128 + cidx]      = fast_tanh(v0.x + v0.y + bias0);
        H[(r0 + r) * 128 + cidx + 64] = fast_tanh(v1.x + v1.y + bias1);
    }
}

// ---------- layer4: H[M][128] @ Wl2[128][32] + b -> prelu -> S12 / out ----------
template<int M, bool FINAL>
DEVINL void layer4(const float* __restrict__ H, const float* __restrict__ WT,
                   const float* __restrict__ bl2, float al,
                   float* __restrict__ S12, float* __restrict__ out,
                   int b0, int nb, int tx, int ty)
{
    constexpr int RPT = M / 16;
    float acc[RPT];
#pragma unroll
    for (int r = 0; r < RPT; r++) acc[r] = 0.0f;
#pragma unroll
    for (int k = 0; k < 128; k += 4) {
        float a[RPT][4];
#pragma unroll
        for (int r = 0; r < RPT; r++) {
            float4 v = *(const float4*)&H[(ty * RPT + r) * 128 + k];
            a[r][0] = v.x; a[r][1] = v.y; a[r][2] = v.z; a[r][3] = v.w;
        }
#pragma unroll
        for (int j = 0; j < 4; j++) {
            float wv = WT[(k + j) * 32 + tx];
#pragma unroll
            for (int r = 0; r < RPT; r++) acc[r] = fmaf(a[r][j], wv, acc[r]);
        }
    }
#pragma unroll
    for (int r = 0; r < RPT; r++) {
        float v = acc[r] + bl2[tx];
        v = (v >= 0.0f) ? v : al * v;
        int row = ty * RPT + r;
        if (FINAL) {
            int be = b0 + (row >> 1);
            if (be < nb) out[(size_t)be * 64 + (row & 1) * 32 + tx] = v;
        } else {
            if (tx < 12) S12[row * 12 + tx] = v;
        }
    }
}

// ---------- full combine() pipeline for M rows ----------
template<int M, bool FINAL>
DEVINL void pipeline(float* sm, int tid,
                     const float* Wc1, const float* bc1, float ac,
                     const float* bc2,
                     const float* Wp1, const float* bp1, float ap,
                     const float* bp2,
                     const float* bl1,
                     const float* Wl2, const float* bl2, float al,
                     float* out, int b0, int nb)
{
    float* U    = sm + SM_U;      // also H (alias)
    float* CHPA = sm + SM_CHPA;
    u64*   WT2  = (u64*)(sm + SM_WT);
    float* WT   = sm + SM_WT;
    float* X    = sm + SM_CHPA;   // alias (consumed before CHPA written)
    float* Y    = sm + SM_Y;
    float* S12  = sm + SM_S12;
    const int tx = tid & 31, ty = tid >> 5;

    // A1: U = prelu(X @ Wc1 + bc1)
    for (int i = tid; i < 24 * 128; i += NTH) WT[i] = Wc1[i];
    __syncthreads();
    layer1<M, 24>(X, WT, bc1, ac, U, tx, ty);
    __syncthreads();
    // B1: ch -> CHPA cols [0,256)
    layer2<M>(U, g_packed + OP_WC2, bc2, CHPA, 0, WT2, tid);
    __syncthreads();
    // A2: V = prelu(Y @ Wp1 + bp1) (overwrites U)
    for (int i = tid; i < 12 * 128; i += NTH) WT[i] = Wp1[i];
    __syncthreads();
    layer1<M, 12>(Y, WT, bp1, ap, U, tx, ty);
    __syncthreads();
    // B2: pa -> CHPA cols [256,512)
    layer2<M>(U, g_packed + OP_WP2, bp2, CHPA, 256, WT2, tid);
    __syncthreads();
    // C: h = tanh(CHPA @ Wl1 + bl1) -> H (aliases U)
    layer3<M>(CHPA, g_packed + OP_WL1, bl1, U, WT2, tid);
    __syncthreads();
    // D: out = prelu(h @ Wl2 + bl2)
    for (int i = tid; i < 128 * 32; i += NTH) WT[i] = Wl2[i];
    __syncthreads();
    layer4<M, FINAL>(U, WT, bl2, al, S12, out, b0, nb, tx, ty);
}

__global__ void __launch_bounds__(NTH, 1)
rvnn_kernel(const float* __restrict__ level1, const float* __restrict__ level2,
            const float* __restrict__ level3,
            const float* __restrict__ Wc1, const float* __restrict__ bc1, const float* __restrict__ ac,
            const float* __restrict__ bc2,
            const float* __restrict__ Wp1, const float* __restrict__ bp1, const float* __restrict__ ap,
            const float* __restrict__ bp2,
            const float* __restrict__ bl1,
            const float* __restrict__ Wl2, const float* __restrict__ bl2, const float* __restrict__ al,
            float* __restrict__ out, int nb)
{
    extern __shared__ float sm[];
    const int tid = threadIdx.x;
    const int b0 = blockIdx.x * BB;
    const float acv = *ac, apv = *ap, alv = *al;

    float* X   = sm + SM_CHPA;
    float* Y   = sm + SM_Y;
    float* S12 = sm + SM_S12;

    // ---- stage 1 input staging ----
    {
        const float* src = level3 + (size_t)b0 * 96;
        int lim = (nb - b0 < BB ? nb - b0 : BB) * 96;
        for (int i = tid; i < BB * 96; i += NTH) {
            float v = (i < lim) ? sanf(src[i]) : 0.0f;
            int be = i / 96, rem = i % 96, c = rem / 12, k = rem % 12;
            int p = c >> 1, s = c & 1;
            X[(be * 4 + p) * 24 + (1 - s) * 12 + k] = v;
        }
    }
    {
        const float* src = level2 + (size_t)b0 * 48;
        int lim = (nb - b0 < BB ? nb - b0 : BB) * 48;
        for (int i = tid; i < BB * 48; i += NTH) {
            float v = (i < lim) ? sanf(src[i]) : 0.0f;
            int be = i / 48, rem = i % 48, p = rem / 12, k = rem % 12;
            Y[(be * 4 + p) * 12 + k] = v;
        }
    }
    __syncthreads();

    pipeline<64, false>(sm, tid, Wc1, bc1, acv, bc2, Wp1, bp1, apv,
                        bp2, bl1, Wl2, bl2, alv, out, b0, nb);
    __syncthreads();

    // ---- stage 2 input staging ----
    for (int i = tid; i < 32 * 24; i += NTH) {
        int r2 = i / 24, k24 = i % 24, be = r2 >> 1, p = r2 & 1;
        int j = 2 * p + (k24 < 12 ? 1 : 0);
        int k = (k24 < 12) ? k24 : (k24 - 12);
        X[r2 * 24 + k24] = sanf(S12[(be * 4 + j) * 12 + k]);
    }
    {
        const float* src = level1 + (size_t)b0 * 24;
        int lim = (nb - b0 < BB ? nb - b0 : BB) * 24;
        for (int i = tid; i < BB * 24; i += NTH) {
            float v = (i < lim) ? sanf(src[i]) : 0.0f;
            int be = i / 24, rem = i % 24, p = rem / 12, k = rem % 12;
            Y[(be * 2 + p) * 12 + k] = v;
        }
    }
    __syncthreads();

    pipeline<32, true>(sm, tid, Wc1, bc1, acv, bc2, Wp1, bp1, apv,
                       bp2, bl1, Wl2, bl2, alv, out, b0, nb);
}

extern "C" void kernel_launch(void* const* d_in, const int* in_sizes, int n_in,
                              void* d_out, int out_size) {
    const float* level1 = (const float*)d_in[0];
    const float* level2 = (const float*)d_in[1];
    const float* level3 = (const float*)d_in[2];
    const float* Wc1 = (const float*)d_in[3];
    const float* bc1 = (const float*)d_in[4];
    const float* ac  = (const float*)d_in[5];
    const float* Wc2 = (const float*)d_in[6];
    const float* bc2 = (const float*)d_in[7];
    const float* Wp1 = (const float*)d_in[8];
    const float* bp1 = (const float*)d_in[9];
    const float* ap  = (const float*)d_in[10];
    const float* Wp2 = (const float*)d_in[11];
    const float* bp2 = (const float*)d_in[12];
    const float* Wl1 = (const float*)d_in[13];
    const float* bl1 = (const float*)d_in[14];
    const float* Wl2 = (const float*)d_in[15];
    const float* bl2 = (const float*)d_in[16];
    const float* al  = (const float*)d_in[17];
    float* out = (float*)d_out;

    int nb = in_sizes[0] / 24;
    int grid = (nb + BB - 1) / BB;
    size_t smem = (size_t)SM_TOT * sizeof(float);  // 202752 B

    prepack_kernel<<<(NPACK + 255) / 256, 256>>>(Wc2, Wp2, Wl1);

    cudaFuncSetAttribute(rvnn_kernel, cudaFuncAttributeMaxDynamicSharedMemorySize, (int)smem);
    rvnn_kernel<<<grid, NTH, smem>>>(level1, level2, level3, Wc1, bc1, ac, bc2,
                                     Wp1, bp1, ap, bp2, bl1, Wl2, bl2, al,
                                     out, nb);
}